// round 14
// baseline (speedup 1.0000x reference)
#include <cuda_runtime.h>

// RSLDS forward-backward smoother, B=8 T=1024 N=64 K=8.
// Outputs: forward | backward | gamma1 | gamma2 (concatenated in d_out).
//
//   pass1: 8x8 transfer-matrix products (R11 shuffle form; rescale every 8)
//   pass2: sequential scan over segments -> boundary vectors
//   fwbwgamma: fw recursion cached in SMEM, then bw recursion + emission.
//          R14: beta kept NORMALIZED — the freed ii=0 reduction slot computes
//          the new beta's normalizer, removing the anchor shuffle + 3 flops.

#define FULLMASK 0xffffffffu
constexpr int B_ = 8, T_ = 1024, N_ = 64, K_ = 8;
constexpr int C_ = B_ * N_;          // 512 chains
constexpr int L_ = 32, S_ = 32;      // segment length, count
constexpr int TN = T_ * N_;
constexpr long long BTNK = (long long)B_ * T_ * N_ * K_;

__device__ float g_Q  [C_ * S_ * 64];  // segment transfer matrices (linear)
__device__ float g_Vb [C_ * S_ * 8];   // fw boundaries (linear, rescaled)
__device__ float g_Rb [C_ * S_ * 8];   // bw boundaries (linear, rescaled)

__device__ __forceinline__ float ex2f(float x) {
    float y; asm("ex2.approx.ftz.f32 %0, %1;" : "=f"(y) : "f"(x)); return y;
}
__device__ __forceinline__ float lg2f(float x) {
    float y; asm("lg2.approx.f32 %0, %1;" : "=f"(y) : "f"(x)); return y;
}
__device__ __forceinline__ float rcpf(float x) {
    float y; asm("rcp.approx.ftz.f32 %0, %1;" : "=f"(y) : "f"(x)); return y;
}

#define L2E 1.4426950408889634f
#define LN2 0.6931471805599453f

// ---------------------------------------------------------------------------
// pass1: Q_s = M_te ... M_ts,  M_t[i,j] = exp(log_b_t[i] + log_a_t[i,j]).
// lane (i = lane>>2, q = lane&3) holds Q[i,2q], Q[i,2q+1].
// Lane loads M row-half [4h..4h+4) with h = q>>1; butterfly xor 2 for the rest.
// ---------------------------------------------------------------------------
__global__ void __launch_bounds__(128) pass1_kernel(
    const float* __restrict__ la, const float* __restrict__ lb)
{
    const int w    = blockIdx.x * 4 + (threadIdx.x >> 5);
    const int lane = threadIdx.x & 31;
    const int q    = lane & 3;
    const int i    = lane >> 2;
    const int h    = q >> 1;
    const int c = w >> 5, s = w & 31;
    const int b = c >> 6, n = c & 63;
    const int tile0 = b * TN + n;

    const int srcL = 16 * h + q;          // Q-gather lanes for local half
    const int srcR = 16 - 16 * h + q;     // and remote half

    const int ts = (s == 0) ? 1 : s * L_;
    const int te = s * L_ + L_ - 1;
    const int cnt = te - ts;              // multiply steps: 30 or 31

    const float4* ap = (const float4*)(la + (size_t)(tile0 + ts * N_) * 64) + i * 2 + h;
    const float*  bp = lb + (tile0 + ts * N_) * 8 + i;

    float Qx, Qy;
    {   // Q = M_ts
        float4 a4 = *ap;
        float  biL = (*bp) * L2E;
        float ax = (q & 1) ? a4.z : a4.x;
        float ay = (q & 1) ? a4.w : a4.y;
        Qx = ex2f(fmaf(ax, L2E, biL));
        Qy = ex2f(fmaf(ay, L2E, biL));
        ap += 16 * N_; bp += 8 * N_;
    }

    // depth-2 prefetch buffers (cnt >= 30 always)
    float4 a4x = ap[0];        float bix = bp[0];
    float4 a4y = ap[16 * N_];  float biy = bp[8 * N_];
    ap += 32 * N_; bp += 16 * N_;

    int rcnt = 0;
    auto mstep = [&](float4 a4, float bi) {
        float biL = bi * L2E;
        float m0 = ex2f(fmaf(a4.x, L2E, biL));
        float m1 = ex2f(fmaf(a4.y, L2E, biL));
        float m2 = ex2f(fmaf(a4.z, L2E, biL));
        float m3 = ex2f(fmaf(a4.w, L2E, biL));
        float o0 = __shfl_xor_sync(FULLMASK, m0, 2);
        float o1 = __shfl_xor_sync(FULLMASK, m1, 2);
        float o2 = __shfl_xor_sync(FULLMASK, m2, 2);
        float o3 = __shfl_xor_sync(FULLMASK, m3, 2);

        float nx = 0.f, ny = 0.f;
        {   // local half: l = 4h + cc
            float qx, qy;
            qx = __shfl_sync(FULLMASK, Qx, srcL);      qy = __shfl_sync(FULLMASK, Qy, srcL);
            nx = fmaf(m0, qx, nx); ny = fmaf(m0, qy, ny);
            qx = __shfl_sync(FULLMASK, Qx, srcL + 4);  qy = __shfl_sync(FULLMASK, Qy, srcL + 4);
            nx = fmaf(m1, qx, nx); ny = fmaf(m1, qy, ny);
            qx = __shfl_sync(FULLMASK, Qx, srcL + 8);  qy = __shfl_sync(FULLMASK, Qy, srcL + 8);
            nx = fmaf(m2, qx, nx); ny = fmaf(m2, qy, ny);
            qx = __shfl_sync(FULLMASK, Qx, srcL + 12); qy = __shfl_sync(FULLMASK, Qy, srcL + 12);
            nx = fmaf(m3, qx, nx); ny = fmaf(m3, qy, ny);
        }
        {   // remote half: l = 4(1-h) + cc
            float qx, qy;
            qx = __shfl_sync(FULLMASK, Qx, srcR);      qy = __shfl_sync(FULLMASK, Qy, srcR);
            nx = fmaf(o0, qx, nx); ny = fmaf(o0, qy, ny);
            qx = __shfl_sync(FULLMASK, Qx, srcR + 4);  qy = __shfl_sync(FULLMASK, Qy, srcR + 4);
            nx = fmaf(o1, qx, nx); ny = fmaf(o1, qy, ny);
            qx = __shfl_sync(FULLMASK, Qx, srcR + 8);  qy = __shfl_sync(FULLMASK, Qy, srcR + 8);
            nx = fmaf(o2, qx, nx); ny = fmaf(o2, qy, ny);
            qx = __shfl_sync(FULLMASK, Qx, srcR + 12); qy = __shfl_sync(FULLMASK, Qy, srcR + 12);
            nx = fmaf(o3, qx, nx); ny = fmaf(o3, qy, ny);
        }
        Qx = nx; Qy = ny;
        ++rcnt;
        if ((rcnt & 7) == 0 || rcnt == cnt) {  // rescale every 8 steps + final
            float m = fmaxf(Qx, Qy);
            m = fmaxf(m, __shfl_xor_sync(FULLMASK, m, 1));
            m = fmaxf(m, __shfl_xor_sync(FULLMASK, m, 2));
            m = fmaxf(m, __shfl_xor_sync(FULLMASK, m, 4));
            m = fmaxf(m, __shfl_xor_sync(FULLMASK, m, 8));
            m = fmaxf(m, __shfl_xor_sync(FULLMASK, m, 16));
            float inv = rcpf(m);
            Qx *= inv; Qy *= inv;
        }
    };

    for (int u = 0; u + 2 <= cnt; u += 2) {
        float4 a = a4x; float bb = bix;
        if (u + 2 < cnt) { a4x = *ap; bix = *bp; ap += 16 * N_; bp += 8 * N_; }
        mstep(a, bb);
        a = a4y; bb = biy;
        if (u + 3 < cnt) { a4y = *ap; biy = *bp; ap += 16 * N_; bp += 8 * N_; }
        mstep(a, bb);
    }
    if (cnt & 1) mstep(a4x, bix);

    *(float2*)(g_Q + (size_t)(c * S_ + s) * 64 + lane * 2) = make_float2(Qx, Qy);
}

// ---------------------------------------------------------------------------
// pass2: sequential scan over segments. warp = (dir, chain).
// ---------------------------------------------------------------------------
__global__ void __launch_bounds__(128) pass2_kernel(
    const float* __restrict__ lb, const float* __restrict__ lz)
{
    const int w    = blockIdx.x * 4 + (threadIdx.x >> 5);
    const int lane = threadIdx.x & 31;
    const int q    = lane & 3;
    const int i    = lane >> 2;
    const bool is_bw = (w >= C_);
    const int c = is_bw ? w - C_ : w;
    const int b = c >> 6, n = c & 63;
    const int tile0 = b * TN + n;

    if (!is_bw) {
        float x = lz[n * 8 + i] + lb[tile0 * 8 + i];
        float m0 = x;
        m0 = fmaxf(m0, __shfl_xor_sync(FULLMASK, m0, 4));
        m0 = fmaxf(m0, __shfl_xor_sync(FULLMASK, m0, 8));
        m0 = fmaxf(m0, __shfl_xor_sync(FULLMASK, m0, 16));
        float vi = ex2f((x - m0) * L2E);       // v[i], replicated over q

        for (int s = 0; s <= 30; s++) {
            float2 Qr = *(const float2*)(g_Q + (size_t)(c * S_ + s) * 64 + lane * 2);
            float vx = __shfl_sync(FULLMASK, vi, 8 * q);
            float vy = __shfl_sync(FULLMASK, vi, 8 * q + 4);
            float p = fmaf(Qr.x, vx, Qr.y * vy);
            p += __shfl_xor_sync(FULLMASK, p, 1);
            p += __shfl_xor_sync(FULLMASK, p, 2);
            float m = p;
            m = fmaxf(m, __shfl_xor_sync(FULLMASK, m, 4));
            m = fmaxf(m, __shfl_xor_sync(FULLMASK, m, 8));
            m = fmaxf(m, __shfl_xor_sync(FULLMASK, m, 16));
            vi = p * rcpf(m);
            if (q == 0) g_Vb[(size_t)(c * S_ + s + 1) * 8 + i] = vi;
        }
    } else {
        float ri = 1.0f;
        for (int s = 31; s >= 1; s--) {
            float2 Qr = *(const float2*)(g_Q + (size_t)(c * S_ + s) * 64 + lane * 2);
            float pe = Qr.x * ri;
            float po = Qr.y * ri;
            pe += __shfl_xor_sync(FULLMASK, pe, 4);
            pe += __shfl_xor_sync(FULLMASK, pe, 8);
            pe += __shfl_xor_sync(FULLMASK, pe, 16);
            po += __shfl_xor_sync(FULLMASK, po, 4);
            po += __shfl_xor_sync(FULLMASK, po, 8);
            po += __shfl_xor_sync(FULLMASK, po, 16);
            float re = __shfl_sync(FULLMASK, pe, i >> 1);
            float ro = __shfl_sync(FULLMASK, po, i >> 1);
            float rn = (i & 1) ? ro : re;
            float m = fmaxf(pe, po);
            m = fmaxf(m, __shfl_xor_sync(FULLMASK, m, 1));
            m = fmaxf(m, __shfl_xor_sync(FULLMASK, m, 2));
            ri = rn * rcpf(m);
            if (q == 0) g_Rb[(size_t)(c * S_ + s) * 8 + i] = ri;
        }
    }
}

// ---------------------------------------------------------------------------
// fwbwgamma: forward recursion (alphas cached in SMEM, 1KB/warp), then
// backward recursion + all output emission in the same warp.
// bw state prev is NORMALIZED log2 beta: the ii=0 reduction slot computes the
// NEW beta's normalizer (ee = e there, no ex2 operand), so no anchor shuffle.
// ii-group stores: 0 -> bw (= prev*LN2), 1 -> fw, 2 -> g1.
// ---------------------------------------------------------------------------
__global__ void __launch_bounds__(128) fwbwgamma_kernel(
    const float* __restrict__ la, const float* __restrict__ lb,
    const float* __restrict__ lz,
    float* __restrict__ fw, float* __restrict__ bwo,
    float* __restrict__ g1, float* __restrict__ g2)
{
    __shared__ float sfw[4 * 264];          // 264-stride staggers banks per warp
    const int wl   = threadIdx.x >> 5;
    const int w    = blockIdx.x * 4 + wl;
    const int lane = threadIdx.x & 31;
    const int ii   = lane & 3;
    const int rr   = lane >> 2;
    const int c = w >> 5, s = w & 31;
    const int b = c >> 6, n = c & 63;
    const int tile0 = b * TN + n;
    const int sel0 = ii * 8, sel1 = ii * 8 + 4;
    const int sL = s * L_;
    const int te = sL + L_ - 1;
    float* fc = sfw + wl * 264;             // fwu cache: [tloc][rr]

    // ===================== forward sweep =====================
    {
        float prev;
        int t0;
        if (s == 0) {
            prev = (lz[n * 8 + rr] + lb[tile0 * 8 + rr]) * L2E;
            if (ii == 0) fc[rr] = prev;     // tloc 0
            t0 = 1;
        } else {
            prev = lg2f(g_Vb[(c * S_ + s) * 8 + rr]);
            t0 = sL;
        }
        const int cnt = te - t0 + 1;        // 31 or 32

        const float2* ap = (const float2*)la + (tile0 + t0 * N_) * 32 + lane;
        const float*  bp = lb + (tile0 + t0 * N_) * 8 + rr;
        float*        op = fc + (t0 - sL) * 8 + rr;

        float2 avx = ap[0];       float bvx = bp[0];
        float2 avy = ap[32 * N_]; float bvy = bp[8 * N_];
        ap += 64 * N_; bp += 16 * N_;

        auto fstep = [&](float2 av, float bv) {
            float p0 = __shfl_sync(FULLMASK, prev, sel0);
            float p1 = __shfl_sync(FULLMASK, prev, sel1);
            float u0 = __shfl_sync(FULLMASK, prev, 0);
            float e = ex2f(fmaf(av.x, L2E, p0 - u0))
                    + ex2f(fmaf(av.y, L2E, p1 - u0));
            e += __shfl_xor_sync(FULLMASK, e, 1);
            e += __shfl_xor_sync(FULLMASK, e, 2);
            float uu = fmaf(bv, L2E, lg2f(e));
            prev = uu;
            if (ii == 0) *op = uu;
            op += 8;
        };

        for (int u = 0; u + 2 <= cnt; u += 2) {
            float2 a = avx; float bb = bvx;
            if (u + 2 < cnt) { avx = *ap; bvx = *bp; ap += 32 * N_; bp += 8 * N_; }
            fstep(a, bb);
            a = avy; bb = bvy;
            if (u + 3 < cnt) { avy = *ap; bvy = *bp; ap += 32 * N_; bp += 8 * N_; }
            fstep(a, bb);
        }
        if (cnt & 1) fstep(avx, bvx);
    }
    __syncwarp();

    // ===================== backward + emission sweep =====================
    const int lnZ = lane | 3;               // same rr, ii=3 lane
    const int lnB = lane & ~3;              // same rr, ii=0 lane
    const bool top = (s == 31);

    // prev = NORMALIZED log2 beta_{te}
    float prev;
    if (top) {
        prev = -3.0f;                        // lg2(1/8): normalized uniform
    } else {
        float pr = lg2f(g_Rb[(c * S_ + s + 1) * 8 + rr]);
        float er = ex2f(pr);
        er += __shfl_xor_sync(FULLMASK, er, 4);
        er += __shfl_xor_sync(FULLMASK, er, 8);
        er += __shfl_xor_sync(FULLMASK, er, 16);
        prev = pr - lg2f(er);
    }
    float fprev = fc[31 * 8 + rr];          // fwu[te]

    const float*  cp  = la + (size_t)(tile0 + te * N_) * 64 + ii * 16 + rr;
    const float2* bp2 = (const float2*)lb + (tile0 + te * N_) * 4 + ii;
    const float*  fp  = fc + 30 * 8 + rr;   // fwu[te-1]
    int ob  = (tile0 + te * N_) * 8 + rr;   // fw/bw/g1 (per-ii predication)
    int g2b = (tile0 + te * N_) * 64;       // gamma2 tile base

    // depth-2 prefetch (31 iterations always)
    float c0x = cp[0], c1x = cp[8];
    float2 bvx = bp2[0];
    float fcx = fp[0];
    float c0y = cp[-64 * N_], c1y = cp[-64 * N_ + 8];
    float2 bvy = bp2[-4 * N_];
    float fcy = fp[-8];
    cp -= 128 * N_; bp2 -= 8 * N_; fp -= 16;

    auto step = [&](float c0, float c1, float2 bv, float fcur, bool first) {
        // recursion core (beta_{t+1} normalized -> e = unnormalized beta_t)
        float p0 = __shfl_sync(FULLMASK, prev, sel0);
        float p1 = __shfl_sync(FULLMASK, prev, sel1);
        float a0 = fmaf(c0 + bv.x, L2E, p0);
        float a1 = fmaf(c1 + bv.y, L2E, p1);
        float e  = ex2f(a0) + ex2f(a1);
        e += __shfl_xor_sync(FULLMASK, e, 1);
        e += __shfl_xor_sync(FULLMASK, e, 2);   // e(rr) = sum over i

        // unified reduction: ii=0 -> NEW beta normalizer (ee = e, no ex2 term);
        // ii=1 -> fw norm; ii=2 -> g1 norm; ii=3 -> gamma2 Z.
        float val = (ii == 1) ? fprev
                  : (ii == 2) ? (fprev + prev) : fcur;
        float ee = (ii == 0) ? e : ex2f(val);
        if (ii == 3) ee *= e;                   // gamma2 Z terms
        ee += __shfl_xor_sync(FULLMASK, ee, 4);
        ee += __shfl_xor_sync(FULLMASK, ee, 8);
        ee += __shfl_xor_sync(FULLMASK, ee, 16);
        float lgE = lg2f(ee);                   // per-ii value
        float lgZ = __shfl_sync(FULLMASK, lgE, lnZ);
        float lgS = __shfl_sync(FULLMASK, lgE, lnB);   // new-beta normalizer

        // emissions for time t+1
        if (ii == 0) bwo[ob] = (top && first) ? 0.0f : prev * LN2;
        else if (ii == 1) fw[ob] = (val - lgE) * LN2;
        else if (ii == 2) g1[ob] = (val - lgE) * LN2;

        float tt2 = (fcur - lgZ) * LN2;
        g2[g2b + 16 * ii + rr]     = fmaf(a0, LN2, tt2);
        g2[g2b + 16 * ii + 8 + rr] = fmaf(a1, LN2, tt2);

        prev  = lg2f(e) - lgS;                  // normalized beta_t
        fprev = fcur;
        ob -= 8 * N_; g2b -= 64 * N_;
    };

    for (int u = 0; u + 2 <= 31; u += 2) {
        {
            float c0 = c0x, c1 = c1x; float2 bv = bvx; float fcv = fcx;
            if (u + 2 < 31) {
                c0x = cp[0]; c1x = cp[8]; bvx = bp2[0]; fcx = fp[0];
                cp -= 64 * N_; bp2 -= 4 * N_; fp -= 8;
            }
            step(c0, c1, bv, fcv, u == 0);
        }
        {
            float c0 = c0y, c1 = c1y; float2 bv = bvy; float fcv = fcy;
            if (u + 3 < 31) {
                c0y = cp[0]; c1y = cp[8]; bvy = bp2[0]; fcy = fp[0];
                cp -= 64 * N_; bp2 -= 4 * N_; fp -= 8;
            }
            step(c0, c1, bv, fcv, false);
        }
    }
    step(c0x, c1x, bvx, fcx, false);           // iteration 30 (odd leftover)

    // ---- tail emission for time t = sL (prev normalized, fprev = fwu[sL]) ----
    {
        float a0t = 0.f, a1t = 0.f, et = 1.0f, fct = 0.f;
        if (s != 0) {
            const float* cpe = la + (size_t)(tile0 + sL * N_) * 64 + ii * 16 + rr;
            float  c0 = cpe[0];
            float  c1 = cpe[8];
            float2 bv = *((const float2*)lb + (tile0 + sL * N_) * 4 + ii);
            fct = lg2f(g_Vb[(c * S_ + s) * 8 + rr]);     // fwu[sL-1] (shifted)
            float p0 = __shfl_sync(FULLMASK, prev, sel0);
            float p1 = __shfl_sync(FULLMASK, prev, sel1);
            a0t = fmaf(c0 + bv.x, L2E, p0);
            a1t = fmaf(c1 + bv.y, L2E, p1);
            et  = ex2f(a0t) + ex2f(a1t);
            et += __shfl_xor_sync(FULLMASK, et, 1);
            et += __shfl_xor_sync(FULLMASK, et, 2);
        }
        float val = (ii == 1) ? fprev
                  : (ii == 2) ? (fprev + prev) : fct;
        float ee = (ii == 0) ? 1.0f : ex2f(val);
        if (ii == 3) ee *= et;
        ee += __shfl_xor_sync(FULLMASK, ee, 4);
        ee += __shfl_xor_sync(FULLMASK, ee, 8);
        ee += __shfl_xor_sync(FULLMASK, ee, 16);
        float lgE = lg2f(ee);
        float lgZ = __shfl_sync(FULLMASK, lgE, lnZ);

        if (ii == 0) bwo[ob] = prev * LN2;
        else if (ii == 1) fw[ob] = (val - lgE) * LN2;
        else if (ii == 2) g1[ob] = (val - lgE) * LN2;

        if (s == 0) {                            // gamma2[0] = zeros
            g2[g2b + 16 * ii + rr]     = 0.0f;
            g2[g2b + 16 * ii + 8 + rr] = 0.0f;
        } else {
            float tt2 = (fct - lgZ) * LN2;
            g2[g2b + 16 * ii + rr]     = fmaf(a0t, LN2, tt2);
            g2[g2b + 16 * ii + 8 + rr] = fmaf(a1t, LN2, tt2);
        }
    }
}

extern "C" void kernel_launch(void* const* d_in, const int* in_sizes, int n_in,
                              void* d_out, int out_size) {
    const float* la = (const float*)d_in[0];   // log_a  (B,T,N,K,K)
    const float* lb = (const float*)d_in[1];   // log_b  (B,T,N,K)
    const float* lz = (const float*)d_in[2];   // logprob_z1 (N,K)

    float* out = (float*)d_out;
    float* fw = out;
    float* bw = fw + BTNK;
    float* g1 = bw + BTNK;
    float* g2 = g1 + BTNK;

    pass1_kernel<<<(C_ * S_) / 4, 128>>>(la, lb);              // 16384 warps
    pass2_kernel<<<(2 * C_) / 4, 128>>>(lb, lz);               // 1024 warps
    fwbwgamma_kernel<<<(C_ * S_) / 4, 128>>>(la, lb, lz, fw, bw, g1, g2);
}

// round 15
// speedup vs baseline: 1.0099x; 1.0099x over previous
#include <cuda_runtime.h>

// RSLDS forward-backward smoother, B=8 T=1024 N=64 K=8.
// Outputs: forward | backward | gamma1 | gamma2 (concatenated in d_out).
//
//   pass1: 8x8 transfer-matrix products. R15: each warp runs TWO independent
//          segments (k, k+16) interleaved — doubles ILP on the latency-bound
//          loop-carried Q chain. Math identical to R12 (rescale every 4).
//   pass2: sequential scan over segments -> boundary vectors  (R12 verbatim)
//   fwbwgamma: fw recursion cached in SMEM, then bw recursion + emission
//          (R12 verbatim — anchored beta, emission reduction off-path).

#define FULLMASK 0xffffffffu
constexpr int B_ = 8, T_ = 1024, N_ = 64, K_ = 8;
constexpr int C_ = B_ * N_;          // 512 chains
constexpr int L_ = 32, S_ = 32;      // segment length, count
constexpr int TN = T_ * N_;
constexpr long long BTNK = (long long)B_ * T_ * N_ * K_;

__device__ float g_Q  [C_ * S_ * 64];  // segment transfer matrices (linear)
__device__ float g_Vb [C_ * S_ * 8];   // fw boundaries (linear, rescaled)
__device__ float g_Rb [C_ * S_ * 8];   // bw boundaries (linear, rescaled)

__device__ __forceinline__ float ex2f(float x) {
    float y; asm("ex2.approx.ftz.f32 %0, %1;" : "=f"(y) : "f"(x)); return y;
}
__device__ __forceinline__ float lg2f(float x) {
    float y; asm("lg2.approx.f32 %0, %1;" : "=f"(y) : "f"(x)); return y;
}
__device__ __forceinline__ float rcpf(float x) {
    float y; asm("rcp.approx.ftz.f32 %0, %1;" : "=f"(y) : "f"(x)); return y;
}

#define L2E 1.4426950408889634f
#define LN2 0.6931471805599453f

// ---------------------------------------------------------------------------
// pass1: Q_s = M_te ... M_ts,  M_t[i,j] = exp(log_b_t[i] + log_a_t[i,j]).
// lane (i = lane>>2, q = lane&3) holds Q[i,2q], Q[i,2q+1].
// Lane loads M row-half [4h..4h+4) with h = q>>1; butterfly xor 2 for the rest.
// R15: warp = (chain c, segment pair {k, k+16}) — two interleaved chains.
// ---------------------------------------------------------------------------
__global__ void __launch_bounds__(128) pass1_kernel(
    const float* __restrict__ la, const float* __restrict__ lb)
{
    const int w    = blockIdx.x * 4 + (threadIdx.x >> 5);
    const int lane = threadIdx.x & 31;
    const int q    = lane & 3;
    const int i    = lane >> 2;
    const int h    = q >> 1;
    const int c = w >> 4, k = w & 15;      // segments k and k+16
    const int b = c >> 6, n = c & 63;
    const int tile0 = b * TN + n;

    const int srcL = 16 * h + q;           // Q-gather lanes for local half
    const int srcR = 16 - 16 * h + q;      // and remote half

    const int tsA = (k == 0) ? 1 : k * L_;
    const int cntA = (k == 0) ? 30 : 31;   // multiply steps after init
    const int tsB = (k + 16) * L_;
    const int cntB = 31;

    const float4* apA = (const float4*)(la + (size_t)(tile0 + tsA * N_) * 64) + i * 2 + h;
    const float*  bpA = lb + (tile0 + tsA * N_) * 8 + i;
    const float4* apB = (const float4*)(la + (size_t)(tile0 + tsB * N_) * 64) + i * 2 + h;
    const float*  bpB = lb + (tile0 + tsB * N_) * 8 + i;

    float QxA, QyA, QxB, QyB;
    {   // Q = M_ts for both chains
        float4 a4 = *apA;
        float  biL = (*bpA) * L2E;
        float ax = (q & 1) ? a4.z : a4.x;
        float ay = (q & 1) ? a4.w : a4.y;
        QxA = ex2f(fmaf(ax, L2E, biL));
        QyA = ex2f(fmaf(ay, L2E, biL));
        apA += 16 * N_; bpA += 8 * N_;
    }
    {
        float4 a4 = *apB;
        float  biL = (*bpB) * L2E;
        float ax = (q & 1) ? a4.z : a4.x;
        float ay = (q & 1) ? a4.w : a4.y;
        QxB = ex2f(fmaf(ax, L2E, biL));
        QyB = ex2f(fmaf(ay, L2E, biL));
        apB += 16 * N_; bpB += 8 * N_;
    }

    // depth-2 prefetch buffers per chain
    float4 a4Ax = apA[0];        float biAx = bpA[0];
    float4 a4Ay = apA[16 * N_];  float biAy = bpA[8 * N_];
    apA += 32 * N_; bpA += 16 * N_;
    float4 a4Bx = apB[0];        float biBx = bpB[0];
    float4 a4By = apB[16 * N_];  float biBy = bpB[8 * N_];
    apB += 32 * N_; bpB += 16 * N_;

    int rcntA = 0, rcntB = 0;
    auto mstep = [&](float& Qx, float& Qy, int& rcnt, int cnt,
                     float4 a4, float bi) {
        float biL = bi * L2E;
        float m0 = ex2f(fmaf(a4.x, L2E, biL));
        float m1 = ex2f(fmaf(a4.y, L2E, biL));
        float m2 = ex2f(fmaf(a4.z, L2E, biL));
        float m3 = ex2f(fmaf(a4.w, L2E, biL));
        float o0 = __shfl_xor_sync(FULLMASK, m0, 2);
        float o1 = __shfl_xor_sync(FULLMASK, m1, 2);
        float o2 = __shfl_xor_sync(FULLMASK, m2, 2);
        float o3 = __shfl_xor_sync(FULLMASK, m3, 2);

        float nx = 0.f, ny = 0.f;
        {   // local half: l = 4h + cc
            float qx, qy;
            qx = __shfl_sync(FULLMASK, Qx, srcL);      qy = __shfl_sync(FULLMASK, Qy, srcL);
            nx = fmaf(m0, qx, nx); ny = fmaf(m0, qy, ny);
            qx = __shfl_sync(FULLMASK, Qx, srcL + 4);  qy = __shfl_sync(FULLMASK, Qy, srcL + 4);
            nx = fmaf(m1, qx, nx); ny = fmaf(m1, qy, ny);
            qx = __shfl_sync(FULLMASK, Qx, srcL + 8);  qy = __shfl_sync(FULLMASK, Qy, srcL + 8);
            nx = fmaf(m2, qx, nx); ny = fmaf(m2, qy, ny);
            qx = __shfl_sync(FULLMASK, Qx, srcL + 12); qy = __shfl_sync(FULLMASK, Qy, srcL + 12);
            nx = fmaf(m3, qx, nx); ny = fmaf(m3, qy, ny);
        }
        {   // remote half: l = 4(1-h) + cc
            float qx, qy;
            qx = __shfl_sync(FULLMASK, Qx, srcR);      qy = __shfl_sync(FULLMASK, Qy, srcR);
            nx = fmaf(o0, qx, nx); ny = fmaf(o0, qy, ny);
            qx = __shfl_sync(FULLMASK, Qx, srcR + 4);  qy = __shfl_sync(FULLMASK, Qy, srcR + 4);
            nx = fmaf(o1, qx, nx); ny = fmaf(o1, qy, ny);
            qx = __shfl_sync(FULLMASK, Qx, srcR + 8);  qy = __shfl_sync(FULLMASK, Qy, srcR + 8);
            nx = fmaf(o2, qx, nx); ny = fmaf(o2, qy, ny);
            qx = __shfl_sync(FULLMASK, Qx, srcR + 12); qy = __shfl_sync(FULLMASK, Qy, srcR + 12);
            nx = fmaf(o3, qx, nx); ny = fmaf(o3, qy, ny);
        }
        Qx = nx; Qy = ny;
        ++rcnt;
        if ((rcnt & 3) == 0 || rcnt == cnt) {  // rescale every 4 + final
            float m = fmaxf(Qx, Qy);
            m = fmaxf(m, __shfl_xor_sync(FULLMASK, m, 1));
            m = fmaxf(m, __shfl_xor_sync(FULLMASK, m, 2));
            m = fmaxf(m, __shfl_xor_sync(FULLMASK, m, 4));
            m = fmaxf(m, __shfl_xor_sync(FULLMASK, m, 8));
            m = fmaxf(m, __shfl_xor_sync(FULLMASK, m, 16));
            float inv = rcpf(m);
            Qx *= inv; Qy *= inv;
        }
    };

    // 30 paired steps (both chains), interleaved A/B for ILP
    for (int u = 0; u + 2 <= 30; u += 2) {
        {
            float4 a = a4Ax; float bb = biAx;
            if (u + 2 < cntA) { a4Ax = *apA; biAx = *bpA; apA += 16 * N_; bpA += 8 * N_; }
            mstep(QxA, QyA, rcntA, cntA, a, bb);
        }
        {
            float4 a = a4Bx; float bb = biBx;
            if (u + 2 < cntB) { a4Bx = *apB; biBx = *bpB; apB += 16 * N_; bpB += 8 * N_; }
            mstep(QxB, QyB, rcntB, cntB, a, bb);
        }
        {
            float4 a = a4Ay; float bb = biAy;
            if (u + 3 < cntA) { a4Ay = *apA; biAy = *bpA; apA += 16 * N_; bpA += 8 * N_; }
            mstep(QxA, QyA, rcntA, cntA, a, bb);
        }
        {
            float4 a = a4By; float bb = biBy;
            if (u + 3 < cntB) { a4By = *apB; biBy = *bpB; apB += 16 * N_; bpB += 8 * N_; }
            mstep(QxB, QyB, rcntB, cntB, a, bb);
        }
    }
    // step 31 (index 30): chain A only if cntA == 31; chain B always
    if (cntA > 30) mstep(QxA, QyA, rcntA, cntA, a4Ax, biAx);
    mstep(QxB, QyB, rcntB, cntB, a4Bx, biBx);

    *(float2*)(g_Q + (size_t)(c * S_ + k) * 64 + lane * 2)        = make_float2(QxA, QyA);
    *(float2*)(g_Q + (size_t)(c * S_ + k + 16) * 64 + lane * 2)   = make_float2(QxB, QyB);
}

// ---------------------------------------------------------------------------
// pass2: sequential scan over segments. warp = (dir, chain).  (R12 verbatim)
// ---------------------------------------------------------------------------
__global__ void __launch_bounds__(128) pass2_kernel(
    const float* __restrict__ lb, const float* __restrict__ lz)
{
    const int w    = blockIdx.x * 4 + (threadIdx.x >> 5);
    const int lane = threadIdx.x & 31;
    const int q    = lane & 3;
    const int i    = lane >> 2;
    const bool is_bw = (w >= C_);
    const int c = is_bw ? w - C_ : w;
    const int b = c >> 6, n = c & 63;
    const int tile0 = b * TN + n;

    if (!is_bw) {
        float x = lz[n * 8 + i] + lb[tile0 * 8 + i];
        float m0 = x;
        m0 = fmaxf(m0, __shfl_xor_sync(FULLMASK, m0, 4));
        m0 = fmaxf(m0, __shfl_xor_sync(FULLMASK, m0, 8));
        m0 = fmaxf(m0, __shfl_xor_sync(FULLMASK, m0, 16));
        float vi = ex2f((x - m0) * L2E);       // v[i], replicated over q

        for (int s = 0; s <= 30; s++) {
            float2 Qr = *(const float2*)(g_Q + (size_t)(c * S_ + s) * 64 + lane * 2);
            float vx = __shfl_sync(FULLMASK, vi, 8 * q);
            float vy = __shfl_sync(FULLMASK, vi, 8 * q + 4);
            float p = fmaf(Qr.x, vx, Qr.y * vy);
            p += __shfl_xor_sync(FULLMASK, p, 1);
            p += __shfl_xor_sync(FULLMASK, p, 2);
            float m = p;
            m = fmaxf(m, __shfl_xor_sync(FULLMASK, m, 4));
            m = fmaxf(m, __shfl_xor_sync(FULLMASK, m, 8));
            m = fmaxf(m, __shfl_xor_sync(FULLMASK, m, 16));
            vi = p * rcpf(m);
            if (q == 0) g_Vb[(size_t)(c * S_ + s + 1) * 8 + i] = vi;
        }
    } else {
        float ri = 1.0f;
        for (int s = 31; s >= 1; s--) {
            float2 Qr = *(const float2*)(g_Q + (size_t)(c * S_ + s) * 64 + lane * 2);
            float pe = Qr.x * ri;
            float po = Qr.y * ri;
            pe += __shfl_xor_sync(FULLMASK, pe, 4);
            pe += __shfl_xor_sync(FULLMASK, pe, 8);
            pe += __shfl_xor_sync(FULLMASK, pe, 16);
            po += __shfl_xor_sync(FULLMASK, po, 4);
            po += __shfl_xor_sync(FULLMASK, po, 8);
            po += __shfl_xor_sync(FULLMASK, po, 16);
            float re = __shfl_sync(FULLMASK, pe, i >> 1);
            float ro = __shfl_sync(FULLMASK, po, i >> 1);
            float rn = (i & 1) ? ro : re;
            float m = fmaxf(pe, po);
            m = fmaxf(m, __shfl_xor_sync(FULLMASK, m, 1));
            m = fmaxf(m, __shfl_xor_sync(FULLMASK, m, 2));
            ri = rn * rcpf(m);
            if (q == 0) g_Rb[(size_t)(c * S_ + s) * 8 + i] = ri;
        }
    }
}

// ---------------------------------------------------------------------------
// fwbwgamma: forward recursion (alphas cached in SMEM, 1KB/warp), then
// backward recursion + all output emission in the same warp. (R12 verbatim)
// ---------------------------------------------------------------------------
__global__ void __launch_bounds__(128) fwbwgamma_kernel(
    const float* __restrict__ la, const float* __restrict__ lb,
    const float* __restrict__ lz,
    float* __restrict__ fw, float* __restrict__ bwo,
    float* __restrict__ g1, float* __restrict__ g2)
{
    __shared__ float sfw[4 * 264];          // 264-stride staggers banks per warp
    const int wl   = threadIdx.x >> 5;
    const int w    = blockIdx.x * 4 + wl;
    const int lane = threadIdx.x & 31;
    const int ii   = lane & 3;
    const int rr   = lane >> 2;
    const int c = w >> 5, s = w & 31;
    const int b = c >> 6, n = c & 63;
    const int tile0 = b * TN + n;
    const int sel0 = ii * 8, sel1 = ii * 8 + 4;
    const int sL = s * L_;
    const int te = sL + L_ - 1;
    float* fc = sfw + wl * 264;             // fwu cache: [tloc][rr]

    // ===================== forward sweep =====================
    {
        float prev;
        int t0;
        if (s == 0) {
            prev = (lz[n * 8 + rr] + lb[tile0 * 8 + rr]) * L2E;
            if (ii == 0) fc[rr] = prev;     // tloc 0
            t0 = 1;
        } else {
            prev = lg2f(g_Vb[(c * S_ + s) * 8 + rr]);
            t0 = sL;
        }
        const int cnt = te - t0 + 1;        // 31 or 32

        const float2* ap = (const float2*)la + (tile0 + t0 * N_) * 32 + lane;
        const float*  bp = lb + (tile0 + t0 * N_) * 8 + rr;
        float*        op = fc + (t0 - sL) * 8 + rr;

        float2 avx = ap[0];       float bvx = bp[0];
        float2 avy = ap[32 * N_]; float bvy = bp[8 * N_];
        ap += 64 * N_; bp += 16 * N_;

        auto fstep = [&](float2 av, float bv) {
            float p0 = __shfl_sync(FULLMASK, prev, sel0);
            float p1 = __shfl_sync(FULLMASK, prev, sel1);
            float u0 = __shfl_sync(FULLMASK, prev, 0);
            float e = ex2f(fmaf(av.x, L2E, p0 - u0))
                    + ex2f(fmaf(av.y, L2E, p1 - u0));
            e += __shfl_xor_sync(FULLMASK, e, 1);
            e += __shfl_xor_sync(FULLMASK, e, 2);
            float uu = fmaf(bv, L2E, lg2f(e));
            prev = uu;
            if (ii == 0) *op = uu;
            op += 8;
        };

        for (int u = 0; u + 2 <= cnt; u += 2) {
            float2 a = avx; float bb = bvx;
            if (u + 2 < cnt) { avx = *ap; bvx = *bp; ap += 32 * N_; bp += 8 * N_; }
            fstep(a, bb);
            a = avy; bb = bvy;
            if (u + 3 < cnt) { avy = *ap; bvy = *bp; ap += 32 * N_; bp += 8 * N_; }
            fstep(a, bb);
        }
        if (cnt & 1) fstep(avx, bvx);
    }
    __syncwarp();

    // ===================== backward + emission sweep =====================
    const int lnZ = lane | 3;               // same rr, ii=3 lane
    const bool top = (s == 31);

    float prev  = top ? 0.0f : lg2f(g_Rb[(c * S_ + s + 1) * 8 + rr]);
    float fprev = fc[31 * 8 + rr];          // fwu[te]

    const float*  cp  = la + (size_t)(tile0 + te * N_) * 64 + ii * 16 + rr;
    const float2* bp2 = (const float2*)lb + (tile0 + te * N_) * 4 + ii;
    const float*  fp  = fc + 30 * 8 + rr;   // fwu[te-1]
    int ob  = (tile0 + te * N_) * 8 + rr;   // fw/bw/g1 (per-ii predication)
    int g2b = (tile0 + te * N_) * 64;       // gamma2 tile base

    // depth-2 prefetch (31 iterations always)
    float c0x = cp[0], c1x = cp[8];
    float2 bvx = bp2[0];
    float fcx = fp[0];
    float c0y = cp[-64 * N_], c1y = cp[-64 * N_ + 8];
    float2 bvy = bp2[-4 * N_];
    float fcy = fp[-8];
    cp -= 128 * N_; bp2 -= 8 * N_; fp -= 16;

    auto step = [&](float c0, float c1, float2 bv, float fcur, bool first) {
        // recursion core (beta_{t+1} -> beta_t)
        float p0 = __shfl_sync(FULLMASK, prev, sel0);
        float p1 = __shfl_sync(FULLMASK, prev, sel1);
        float u0 = __shfl_sync(FULLMASK, prev, 0);
        float a0 = fmaf(c0 + bv.x, L2E, p0 - u0);
        float a1 = fmaf(c1 + bv.y, L2E, p1 - u0);
        float e  = ex2f(a0) + ex2f(a1);
        e += __shfl_xor_sync(FULLMASK, e, 1);
        e += __shfl_xor_sync(FULLMASK, e, 2);   // e(rr) = sum over i

        // unified emission reduction for time t+1 (per-ii operand)
        float val = (ii == 0) ? prev
                  : (ii == 1) ? fprev
                  : (ii == 2) ? (fprev + prev) : fcur;
        float ee = ex2f(val);
        if (ii == 3) ee *= e;                   // gamma2 Z terms
        ee += __shfl_xor_sync(FULLMASK, ee, 4);
        ee += __shfl_xor_sync(FULLMASK, ee, 8);
        ee += __shfl_xor_sync(FULLMASK, ee, 16);
        float lgE = lg2f(ee);                   // per-ii normalizer
        float lgZ = __shfl_sync(FULLMASK, lgE, lnZ);

        float outv = (val - lgE) * LN2;
        if (ii == 0) bwo[ob] = (top && first) ? 0.0f : outv;
        else if (ii == 1) fw[ob] = outv;
        else if (ii == 2) g1[ob] = outv;

        float tt2 = (fcur - lgZ) * LN2;
        g2[g2b + 16 * ii + rr]     = fmaf(a0, LN2, tt2);
        g2[g2b + 16 * ii + 8 + rr] = fmaf(a1, LN2, tt2);

        prev  = lg2f(e);
        fprev = fcur;
        ob -= 8 * N_; g2b -= 64 * N_;
    };

    for (int u = 0; u + 2 <= 31; u += 2) {
        {
            float c0 = c0x, c1 = c1x; float2 bv = bvx; float fcv = fcx;
            if (u + 2 < 31) {
                c0x = cp[0]; c1x = cp[8]; bvx = bp2[0]; fcx = fp[0];
                cp -= 64 * N_; bp2 -= 4 * N_; fp -= 8;
            }
            step(c0, c1, bv, fcv, u == 0);
        }
        {
            float c0 = c0y, c1 = c1y; float2 bv = bvy; float fcv = fcy;
            if (u + 3 < 31) {
                c0y = cp[0]; c1y = cp[8]; bvy = bp2[0]; fcy = fp[0];
                cp -= 64 * N_; bp2 -= 4 * N_; fp -= 8;
            }
            step(c0, c1, bv, fcv, false);
        }
    }
    step(c0x, c1x, bvx, fcx, false);           // iteration 30 (odd leftover)

    // ---- tail emission for time t = sL (prev = beta_{sL}, fprev = fwu[sL]) ----
    {
        float a0t = 0.f, a1t = 0.f, et = 1.0f, fct = 0.f;
        if (s != 0) {
            const float* cpe = la + (size_t)(tile0 + sL * N_) * 64 + ii * 16 + rr;
            float  c0 = cpe[0];
            float  c1 = cpe[8];
            float2 bv = *((const float2*)lb + (tile0 + sL * N_) * 4 + ii);
            fct = lg2f(g_Vb[(c * S_ + s) * 8 + rr]);     // fwu[sL-1] (shifted)
            float p0 = __shfl_sync(FULLMASK, prev, sel0);
            float p1 = __shfl_sync(FULLMASK, prev, sel1);
            float u0 = __shfl_sync(FULLMASK, prev, 0);
            a0t = fmaf(c0 + bv.x, L2E, p0 - u0);
            a1t = fmaf(c1 + bv.y, L2E, p1 - u0);
            et  = ex2f(a0t) + ex2f(a1t);
            et += __shfl_xor_sync(FULLMASK, et, 1);
            et += __shfl_xor_sync(FULLMASK, et, 2);
        }
        float val = (ii == 0) ? prev
                  : (ii == 1) ? fprev
                  : (ii == 2) ? (fprev + prev) : fct;
        float ee = ex2f(val);
        if (ii == 3) ee *= et;
        ee += __shfl_xor_sync(FULLMASK, ee, 4);
        ee += __shfl_xor_sync(FULLMASK, ee, 8);
        ee += __shfl_xor_sync(FULLMASK, ee, 16);
        float lgE = lg2f(ee);
        float lgZ = __shfl_sync(FULLMASK, lgE, lnZ);

        float outv = (val - lgE) * LN2;
        if (ii == 0) bwo[ob] = outv;
        else if (ii == 1) fw[ob] = outv;
        else if (ii == 2) g1[ob] = outv;

        if (s == 0) {                            // gamma2[0] = zeros
            g2[g2b + 16 * ii + rr]     = 0.0f;
            g2[g2b + 16 * ii + 8 + rr] = 0.0f;
        } else {
            float tt2 = (fct - lgZ) * LN2;
            g2[g2b + 16 * ii + rr]     = fmaf(a0t, LN2, tt2);
            g2[g2b + 16 * ii + 8 + rr] = fmaf(a1t, LN2, tt2);
        }
    }
}

extern "C" void kernel_launch(void* const* d_in, const int* in_sizes, int n_in,
                              void* d_out, int out_size) {
    const float* la = (const float*)d_in[0];   // log_a  (B,T,N,K,K)
    const float* lb = (const float*)d_in[1];   // log_b  (B,T,N,K)
    const float* lz = (const float*)d_in[2];   // logprob_z1 (N,K)

    float* out = (float*)d_out;
    float* fw = out;
    float* bw = fw + BTNK;
    float* g1 = bw + BTNK;
    float* g2 = g1 + BTNK;

    pass1_kernel<<<(C_ * S_ / 2) / 4, 128>>>(la, lb);          // 8192 dual-chain warps
    pass2_kernel<<<(2 * C_) / 4, 128>>>(lb, lz);               // 1024 warps
    fwbwgamma_kernel<<<(C_ * S_) / 4, 128>>>(la, lb, lz, fw, bw, g1, g2);
}

// round 16
// speedup vs baseline: 1.0358x; 1.0256x over previous
#include <cuda_runtime.h>

// RSLDS forward-backward smoother, B=8 T=1024 N=64 K=8.
// Outputs: forward | backward | gamma1 | gamma2 (concatenated in d_out).
//
//   pass1: 8x8 transfer-matrix products. R16: lane loads its FULL M row
//          (2x LDG.128, same L1 lines) — removes the 4 butterfly shuffles:
//          20 -> 16 shfl/step on the binding SHFL pipe. Rescale every 4.
//   pass2: sequential scan over segments -> boundary vectors  (R12 verbatim)
//   fwbwgamma: fw recursion cached in SMEM, then bw recursion + emission
//          (R12 verbatim — anchored beta, off-path unified emission reduction).

#define FULLMASK 0xffffffffu
constexpr int B_ = 8, T_ = 1024, N_ = 64, K_ = 8;
constexpr int C_ = B_ * N_;          // 512 chains
constexpr int L_ = 32, S_ = 32;      // segment length, count
constexpr int TN = T_ * N_;
constexpr long long BTNK = (long long)B_ * T_ * N_ * K_;

__device__ float g_Q  [C_ * S_ * 64];  // segment transfer matrices (linear)
__device__ float g_Vb [C_ * S_ * 8];   // fw boundaries (linear, rescaled)
__device__ float g_Rb [C_ * S_ * 8];   // bw boundaries (linear, rescaled)

__device__ __forceinline__ float ex2f(float x) {
    float y; asm("ex2.approx.ftz.f32 %0, %1;" : "=f"(y) : "f"(x)); return y;
}
__device__ __forceinline__ float lg2f(float x) {
    float y; asm("lg2.approx.f32 %0, %1;" : "=f"(y) : "f"(x)); return y;
}
__device__ __forceinline__ float rcpf(float x) {
    float y; asm("rcp.approx.ftz.f32 %0, %1;" : "=f"(y) : "f"(x)); return y;
}

#define L2E 1.4426950408889634f
#define LN2 0.6931471805599453f

// ---------------------------------------------------------------------------
// pass1: Q_s = M_te ... M_ts,  M_t[i,j] = exp(log_b_t[i] + log_a_t[i,j]).
// lane (i = lane>>2, q = lane&3) holds Q[i,2q], Q[i,2q+1] and loads the FULL
// row i of M each step (no butterfly exchange). 16 Q-gather shuffles/step.
// ---------------------------------------------------------------------------
__global__ void __launch_bounds__(128) pass1_kernel(
    const float* __restrict__ la, const float* __restrict__ lb)
{
    const int w    = blockIdx.x * 4 + (threadIdx.x >> 5);
    const int lane = threadIdx.x & 31;
    const int q    = lane & 3;
    const int i    = lane >> 2;
    const int c = w >> 5, s = w & 31;
    const int b = c >> 6, n = c & 63;
    const int tile0 = b * TN + n;

    const int ts = (s == 0) ? 1 : s * L_;
    const int te = s * L_ + L_ - 1;
    const int cnt = te - ts;              // multiply steps: 30 or 31

    // full row i: cols 0..3 at +2i, cols 4..7 at +2i+1 (float4 units)
    const float4* ap = (const float4*)(la + (size_t)(tile0 + ts * N_) * 64) + i * 2;
    const float*  bp = lb + (tile0 + ts * N_) * 8 + i;

    float Qx, Qy;
    {   // Q = M_ts : select own pair (2q, 2q+1) from the full row
        float4 lo = ap[0];
        float4 hi = ap[1];
        float  biL = (*bp) * L2E;
        float ax = (q == 0) ? lo.x : (q == 1) ? lo.z : (q == 2) ? hi.x : hi.z;
        float ay = (q == 0) ? lo.y : (q == 1) ? lo.w : (q == 2) ? hi.y : hi.w;
        Qx = ex2f(fmaf(ax, L2E, biL));
        Qy = ex2f(fmaf(ay, L2E, biL));
        ap += 16 * N_; bp += 8 * N_;
    }

    // depth-2 prefetch buffers (cnt >= 30 always)
    float4 lox = ap[0], hix = ap[1];          float bix = bp[0];
    float4 loy = ap[16 * N_], hiy = ap[16 * N_ + 1]; float biy = bp[8 * N_];
    ap += 32 * N_; bp += 16 * N_;

    int rcnt = 0;
    auto mstep = [&](float4 lo, float4 hi, float bi) {
        float biL = bi * L2E;
        float m0 = ex2f(fmaf(lo.x, L2E, biL));
        float m1 = ex2f(fmaf(lo.y, L2E, biL));
        float m2 = ex2f(fmaf(lo.z, L2E, biL));
        float m3 = ex2f(fmaf(lo.w, L2E, biL));
        float m4 = ex2f(fmaf(hi.x, L2E, biL));
        float m5 = ex2f(fmaf(hi.y, L2E, biL));
        float m6 = ex2f(fmaf(hi.z, L2E, biL));
        float m7 = ex2f(fmaf(hi.w, L2E, biL));

        // Q columns 2q, 2q+1 gathered across the 8 row-groups (16 shuffles)
        float nxa = 0.f, nya = 0.f, nxb = 0.f, nyb = 0.f;
        float qx, qy;
        qx = __shfl_sync(FULLMASK, Qx, q);       qy = __shfl_sync(FULLMASK, Qy, q);
        nxa = fmaf(m0, qx, nxa); nya = fmaf(m0, qy, nya);
        qx = __shfl_sync(FULLMASK, Qx, q + 4);   qy = __shfl_sync(FULLMASK, Qy, q + 4);
        nxa = fmaf(m1, qx, nxa); nya = fmaf(m1, qy, nya);
        qx = __shfl_sync(FULLMASK, Qx, q + 8);   qy = __shfl_sync(FULLMASK, Qy, q + 8);
        nxa = fmaf(m2, qx, nxa); nya = fmaf(m2, qy, nya);
        qx = __shfl_sync(FULLMASK, Qx, q + 12);  qy = __shfl_sync(FULLMASK, Qy, q + 12);
        nxa = fmaf(m3, qx, nxa); nya = fmaf(m3, qy, nya);
        qx = __shfl_sync(FULLMASK, Qx, q + 16);  qy = __shfl_sync(FULLMASK, Qy, q + 16);
        nxb = fmaf(m4, qx, nxb); nyb = fmaf(m4, qy, nyb);
        qx = __shfl_sync(FULLMASK, Qx, q + 20);  qy = __shfl_sync(FULLMASK, Qy, q + 20);
        nxb = fmaf(m5, qx, nxb); nyb = fmaf(m5, qy, nyb);
        qx = __shfl_sync(FULLMASK, Qx, q + 24);  qy = __shfl_sync(FULLMASK, Qy, q + 24);
        nxb = fmaf(m6, qx, nxb); nyb = fmaf(m6, qy, nyb);
        qx = __shfl_sync(FULLMASK, Qx, q + 28);  qy = __shfl_sync(FULLMASK, Qy, q + 28);
        nxb = fmaf(m7, qx, nxb); nyb = fmaf(m7, qy, nyb);

        float nx = nxa + nxb;
        float ny = nya + nyb;
        ++rcnt;
        if ((rcnt & 3) == 0 || rcnt == cnt) {  // rescale every 4 + final
            float m = fmaxf(nx, ny);
            m = fmaxf(m, __shfl_xor_sync(FULLMASK, m, 1));
            m = fmaxf(m, __shfl_xor_sync(FULLMASK, m, 2));
            m = fmaxf(m, __shfl_xor_sync(FULLMASK, m, 4));
            m = fmaxf(m, __shfl_xor_sync(FULLMASK, m, 8));
            m = fmaxf(m, __shfl_xor_sync(FULLMASK, m, 16));
            float inv = rcpf(m);
            nx *= inv; ny *= inv;
        }
        Qx = nx; Qy = ny;
    };

    for (int u = 0; u + 2 <= cnt; u += 2) {
        float4 l = lox, h2 = hix; float bb = bix;
        if (u + 2 < cnt) { lox = ap[0]; hix = ap[1]; bix = *bp; ap += 16 * N_; bp += 8 * N_; }
        mstep(l, h2, bb);
        l = loy; h2 = hiy; bb = biy;
        if (u + 3 < cnt) { loy = ap[0]; hiy = ap[1]; biy = *bp; ap += 16 * N_; bp += 8 * N_; }
        mstep(l, h2, bb);
    }
    if (cnt & 1) mstep(lox, hix, bix);

    *(float2*)(g_Q + (size_t)(c * S_ + s) * 64 + lane * 2) = make_float2(Qx, Qy);
}

// ---------------------------------------------------------------------------
// pass2: sequential scan over segments. warp = (dir, chain).  (R12 verbatim)
// ---------------------------------------------------------------------------
__global__ void __launch_bounds__(128) pass2_kernel(
    const float* __restrict__ lb, const float* __restrict__ lz)
{
    const int w    = blockIdx.x * 4 + (threadIdx.x >> 5);
    const int lane = threadIdx.x & 31;
    const int q    = lane & 3;
    const int i    = lane >> 2;
    const bool is_bw = (w >= C_);
    const int c = is_bw ? w - C_ : w;
    const int b = c >> 6, n = c & 63;
    const int tile0 = b * TN + n;

    if (!is_bw) {
        float x = lz[n * 8 + i] + lb[tile0 * 8 + i];
        float m0 = x;
        m0 = fmaxf(m0, __shfl_xor_sync(FULLMASK, m0, 4));
        m0 = fmaxf(m0, __shfl_xor_sync(FULLMASK, m0, 8));
        m0 = fmaxf(m0, __shfl_xor_sync(FULLMASK, m0, 16));
        float vi = ex2f((x - m0) * L2E);       // v[i], replicated over q

        for (int s = 0; s <= 30; s++) {
            float2 Qr = *(const float2*)(g_Q + (size_t)(c * S_ + s) * 64 + lane * 2);
            float vx = __shfl_sync(FULLMASK, vi, 8 * q);
            float vy = __shfl_sync(FULLMASK, vi, 8 * q + 4);
            float p = fmaf(Qr.x, vx, Qr.y * vy);
            p += __shfl_xor_sync(FULLMASK, p, 1);
            p += __shfl_xor_sync(FULLMASK, p, 2);
            float m = p;
            m = fmaxf(m, __shfl_xor_sync(FULLMASK, m, 4));
            m = fmaxf(m, __shfl_xor_sync(FULLMASK, m, 8));
            m = fmaxf(m, __shfl_xor_sync(FULLMASK, m, 16));
            vi = p * rcpf(m);
            if (q == 0) g_Vb[(size_t)(c * S_ + s + 1) * 8 + i] = vi;
        }
    } else {
        float ri = 1.0f;
        for (int s = 31; s >= 1; s--) {
            float2 Qr = *(const float2*)(g_Q + (size_t)(c * S_ + s) * 64 + lane * 2);
            float pe = Qr.x * ri;
            float po = Qr.y * ri;
            pe += __shfl_xor_sync(FULLMASK, pe, 4);
            pe += __shfl_xor_sync(FULLMASK, pe, 8);
            pe += __shfl_xor_sync(FULLMASK, pe, 16);
            po += __shfl_xor_sync(FULLMASK, po, 4);
            po += __shfl_xor_sync(FULLMASK, po, 8);
            po += __shfl_xor_sync(FULLMASK, po, 16);
            float re = __shfl_sync(FULLMASK, pe, i >> 1);
            float ro = __shfl_sync(FULLMASK, po, i >> 1);
            float rn = (i & 1) ? ro : re;
            float m = fmaxf(pe, po);
            m = fmaxf(m, __shfl_xor_sync(FULLMASK, m, 1));
            m = fmaxf(m, __shfl_xor_sync(FULLMASK, m, 2));
            ri = rn * rcpf(m);
            if (q == 0) g_Rb[(size_t)(c * S_ + s) * 8 + i] = ri;
        }
    }
}

// ---------------------------------------------------------------------------
// fwbwgamma: forward recursion (alphas cached in SMEM, 1KB/warp), then
// backward recursion + all output emission in the same warp. (R12 verbatim)
// ---------------------------------------------------------------------------
__global__ void __launch_bounds__(128) fwbwgamma_kernel(
    const float* __restrict__ la, const float* __restrict__ lb,
    const float* __restrict__ lz,
    float* __restrict__ fw, float* __restrict__ bwo,
    float* __restrict__ g1, float* __restrict__ g2)
{
    __shared__ float sfw[4 * 264];          // 264-stride staggers banks per warp
    const int wl   = threadIdx.x >> 5;
    const int w    = blockIdx.x * 4 + wl;
    const int lane = threadIdx.x & 31;
    const int ii   = lane & 3;
    const int rr   = lane >> 2;
    const int c = w >> 5, s = w & 31;
    const int b = c >> 6, n = c & 63;
    const int tile0 = b * TN + n;
    const int sel0 = ii * 8, sel1 = ii * 8 + 4;
    const int sL = s * L_;
    const int te = sL + L_ - 1;
    float* fc = sfw + wl * 264;             // fwu cache: [tloc][rr]

    // ===================== forward sweep =====================
    {
        float prev;
        int t0;
        if (s == 0) {
            prev = (lz[n * 8 + rr] + lb[tile0 * 8 + rr]) * L2E;
            if (ii == 0) fc[rr] = prev;     // tloc 0
            t0 = 1;
        } else {
            prev = lg2f(g_Vb[(c * S_ + s) * 8 + rr]);
            t0 = sL;
        }
        const int cnt = te - t0 + 1;        // 31 or 32

        const float2* ap = (const float2*)la + (tile0 + t0 * N_) * 32 + lane;
        const float*  bp = lb + (tile0 + t0 * N_) * 8 + rr;
        float*        op = fc + (t0 - sL) * 8 + rr;

        float2 avx = ap[0];       float bvx = bp[0];
        float2 avy = ap[32 * N_]; float bvy = bp[8 * N_];
        ap += 64 * N_; bp += 16 * N_;

        auto fstep = [&](float2 av, float bv) {
            float p0 = __shfl_sync(FULLMASK, prev, sel0);
            float p1 = __shfl_sync(FULLMASK, prev, sel1);
            float u0 = __shfl_sync(FULLMASK, prev, 0);
            float e = ex2f(fmaf(av.x, L2E, p0 - u0))
                    + ex2f(fmaf(av.y, L2E, p1 - u0));
            e += __shfl_xor_sync(FULLMASK, e, 1);
            e += __shfl_xor_sync(FULLMASK, e, 2);
            float uu = fmaf(bv, L2E, lg2f(e));
            prev = uu;
            if (ii == 0) *op = uu;
            op += 8;
        };

        for (int u = 0; u + 2 <= cnt; u += 2) {
            float2 a = avx; float bb = bvx;
            if (u + 2 < cnt) { avx = *ap; bvx = *bp; ap += 32 * N_; bp += 8 * N_; }
            fstep(a, bb);
            a = avy; bb = bvy;
            if (u + 3 < cnt) { avy = *ap; bvy = *bp; ap += 32 * N_; bp += 8 * N_; }
            fstep(a, bb);
        }
        if (cnt & 1) fstep(avx, bvx);
    }
    __syncwarp();

    // ===================== backward + emission sweep =====================
    const int lnZ = lane | 3;               // same rr, ii=3 lane
    const bool top = (s == 31);

    float prev  = top ? 0.0f : lg2f(g_Rb[(c * S_ + s + 1) * 8 + rr]);
    float fprev = fc[31 * 8 + rr];          // fwu[te]

    const float*  cp  = la + (size_t)(tile0 + te * N_) * 64 + ii * 16 + rr;
    const float2* bp2 = (const float2*)lb + (tile0 + te * N_) * 4 + ii;
    const float*  fp  = fc + 30 * 8 + rr;   // fwu[te-1]
    int ob  = (tile0 + te * N_) * 8 + rr;   // fw/bw/g1 (per-ii predication)
    int g2b = (tile0 + te * N_) * 64;       // gamma2 tile base

    // depth-2 prefetch (31 iterations always)
    float c0x = cp[0], c1x = cp[8];
    float2 bvx = bp2[0];
    float fcx = fp[0];
    float c0y = cp[-64 * N_], c1y = cp[-64 * N_ + 8];
    float2 bvy = bp2[-4 * N_];
    float fcy = fp[-8];
    cp -= 128 * N_; bp2 -= 8 * N_; fp -= 16;

    auto step = [&](float c0, float c1, float2 bv, float fcur, bool first) {
        // recursion core (beta_{t+1} -> beta_t)
        float p0 = __shfl_sync(FULLMASK, prev, sel0);
        float p1 = __shfl_sync(FULLMASK, prev, sel1);
        float u0 = __shfl_sync(FULLMASK, prev, 0);
        float a0 = fmaf(c0 + bv.x, L2E, p0 - u0);
        float a1 = fmaf(c1 + bv.y, L2E, p1 - u0);
        float e  = ex2f(a0) + ex2f(a1);
        e += __shfl_xor_sync(FULLMASK, e, 1);
        e += __shfl_xor_sync(FULLMASK, e, 2);   // e(rr) = sum over i

        // unified emission reduction for time t+1 (per-ii operand)
        float val = (ii == 0) ? prev
                  : (ii == 1) ? fprev
                  : (ii == 2) ? (fprev + prev) : fcur;
        float ee = ex2f(val);
        if (ii == 3) ee *= e;                   // gamma2 Z terms
        ee += __shfl_xor_sync(FULLMASK, ee, 4);
        ee += __shfl_xor_sync(FULLMASK, ee, 8);
        ee += __shfl_xor_sync(FULLMASK, ee, 16);
        float lgE = lg2f(ee);                   // per-ii normalizer
        float lgZ = __shfl_sync(FULLMASK, lgE, lnZ);

        float outv = (val - lgE) * LN2;
        if (ii == 0) bwo[ob] = (top && first) ? 0.0f : outv;
        else if (ii == 1) fw[ob] = outv;
        else if (ii == 2) g1[ob] = outv;

        float tt2 = (fcur - lgZ) * LN2;
        g2[g2b + 16 * ii + rr]     = fmaf(a0, LN2, tt2);
        g2[g2b + 16 * ii + 8 + rr] = fmaf(a1, LN2, tt2);

        prev  = lg2f(e);
        fprev = fcur;
        ob -= 8 * N_; g2b -= 64 * N_;
    };

    for (int u = 0; u + 2 <= 31; u += 2) {
        {
            float c0 = c0x, c1 = c1x; float2 bv = bvx; float fcv = fcx;
            if (u + 2 < 31) {
                c0x = cp[0]; c1x = cp[8]; bvx = bp2[0]; fcx = fp[0];
                cp -= 64 * N_; bp2 -= 4 * N_; fp -= 8;
            }
            step(c0, c1, bv, fcv, u == 0);
        }
        {
            float c0 = c0y, c1 = c1y; float2 bv = bvy; float fcv = fcy;
            if (u + 3 < 31) {
                c0y = cp[0]; c1y = cp[8]; bvy = bp2[0]; fcy = fp[0];
                cp -= 64 * N_; bp2 -= 4 * N_; fp -= 8;
            }
            step(c0, c1, bv, fcv, false);
        }
    }
    step(c0x, c1x, bvx, fcx, false);           // iteration 30 (odd leftover)

    // ---- tail emission for time t = sL (prev = beta_{sL}, fprev = fwu[sL]) ----
    {
        float a0t = 0.f, a1t = 0.f, et = 1.0f, fct = 0.f;
        if (s != 0) {
            const float* cpe = la + (size_t)(tile0 + sL * N_) * 64 + ii * 16 + rr;
            float  c0 = cpe[0];
            float  c1 = cpe[8];
            float2 bv = *((const float2*)lb + (tile0 + sL * N_) * 4 + ii);
            fct = lg2f(g_Vb[(c * S_ + s) * 8 + rr]);     // fwu[sL-1] (shifted)
            float p0 = __shfl_sync(FULLMASK, prev, sel0);
            float p1 = __shfl_sync(FULLMASK, prev, sel1);
            float u0 = __shfl_sync(FULLMASK, prev, 0);
            a0t = fmaf(c0 + bv.x, L2E, p0 - u0);
            a1t = fmaf(c1 + bv.y, L2E, p1 - u0);
            et  = ex2f(a0t) + ex2f(a1t);
            et += __shfl_xor_sync(FULLMASK, et, 1);
            et += __shfl_xor_sync(FULLMASK, et, 2);
        }
        float val = (ii == 0) ? prev
                  : (ii == 1) ? fprev
                  : (ii == 2) ? (fprev + prev) : fct;
        float ee = ex2f(val);
        if (ii == 3) ee *= et;
        ee += __shfl_xor_sync(FULLMASK, ee, 4);
        ee += __shfl_xor_sync(FULLMASK, ee, 8);
        ee += __shfl_xor_sync(FULLMASK, ee, 16);
        float lgE = lg2f(ee);
        float lgZ = __shfl_sync(FULLMASK, lgE, lnZ);

        float outv = (val - lgE) * LN2;
        if (ii == 0) bwo[ob] = outv;
        else if (ii == 1) fw[ob] = outv;
        else if (ii == 2) g1[ob] = outv;

        if (s == 0) {                            // gamma2[0] = zeros
            g2[g2b + 16 * ii + rr]     = 0.0f;
            g2[g2b + 16 * ii + 8 + rr] = 0.0f;
        } else {
            float tt2 = (fct - lgZ) * LN2;
            g2[g2b + 16 * ii + rr]     = fmaf(a0t, LN2, tt2);
            g2[g2b + 16 * ii + 8 + rr] = fmaf(a1t, LN2, tt2);
        }
    }
}

extern "C" void kernel_launch(void* const* d_in, const int* in_sizes, int n_in,
                              void* d_out, int out_size) {
    const float* la = (const float*)d_in[0];   // log_a  (B,T,N,K,K)
    const float* lb = (const float*)d_in[1];   // log_b  (B,T,N,K)
    const float* lz = (const float*)d_in[2];   // logprob_z1 (N,K)

    float* out = (float*)d_out;
    float* fw = out;
    float* bw = fw + BTNK;
    float* g1 = bw + BTNK;
    float* g2 = g1 + BTNK;

    pass1_kernel<<<(C_ * S_) / 4, 128>>>(la, lb);              // 16384 warps
    pass2_kernel<<<(2 * C_) / 4, 128>>>(lb, lz);               // 1024 warps
    fwbwgamma_kernel<<<(C_ * S_) / 4, 128>>>(la, lb, lz, fw, bw, g1, g2);
}

// round 17
// speedup vs baseline: 1.1012x; 1.0631x over previous
#include <cuda_runtime.h>

// RSLDS forward-backward smoother, B=8 T=1024 N=64 K=8.
// Outputs: forward | backward | gamma1 | gamma2 (concatenated in d_out).
//
//   pass1: 8x8 transfer-matrix products (R12-best: half-row float4 loads +
//          butterfly xor-2, 20 shfl/step, rescale every 4).
//          R17: __launch_bounds__(128,10) caps regs at 51 -> 40 warps/SM.
//   pass2: sequential scan over segments -> boundary vectors  (R12 verbatim)
//   fwbwgamma: fw recursion cached in SMEM, then bw recursion + emission
//          (R12 verbatim — anchored beta, off-path unified emission reduction).

#define FULLMASK 0xffffffffu
constexpr int B_ = 8, T_ = 1024, N_ = 64, K_ = 8;
constexpr int C_ = B_ * N_;          // 512 chains
constexpr int L_ = 32, S_ = 32;      // segment length, count
constexpr int TN = T_ * N_;
constexpr long long BTNK = (long long)B_ * T_ * N_ * K_;

__device__ float g_Q  [C_ * S_ * 64];  // segment transfer matrices (linear)
__device__ float g_Vb [C_ * S_ * 8];   // fw boundaries (linear, rescaled)
__device__ float g_Rb [C_ * S_ * 8];   // bw boundaries (linear, rescaled)

__device__ __forceinline__ float ex2f(float x) {
    float y; asm("ex2.approx.ftz.f32 %0, %1;" : "=f"(y) : "f"(x)); return y;
}
__device__ __forceinline__ float lg2f(float x) {
    float y; asm("lg2.approx.f32 %0, %1;" : "=f"(y) : "f"(x)); return y;
}
__device__ __forceinline__ float rcpf(float x) {
    float y; asm("rcp.approx.ftz.f32 %0, %1;" : "=f"(y) : "f"(x)); return y;
}

#define L2E 1.4426950408889634f
#define LN2 0.6931471805599453f

// ---------------------------------------------------------------------------
// pass1: Q_s = M_te ... M_ts,  M_t[i,j] = exp(log_b_t[i] + log_a_t[i,j]).
// lane (i = lane>>2, q = lane&3) holds Q[i,2q], Q[i,2q+1].
// Lane loads M row-half [4h..4h+4) with h = q>>1; butterfly xor 2 for the rest.
// ---------------------------------------------------------------------------
__global__ void __launch_bounds__(128, 10) pass1_kernel(
    const float* __restrict__ la, const float* __restrict__ lb)
{
    const int w    = blockIdx.x * 4 + (threadIdx.x >> 5);
    const int lane = threadIdx.x & 31;
    const int q    = lane & 3;
    const int i    = lane >> 2;
    const int h    = q >> 1;
    const int c = w >> 5, s = w & 31;
    const int b = c >> 6, n = c & 63;
    const int tile0 = b * TN + n;

    const int srcL = 16 * h + q;          // Q-gather lanes for local half
    const int srcR = 16 - 16 * h + q;     // and remote half

    const int ts = (s == 0) ? 1 : s * L_;
    const int te = s * L_ + L_ - 1;
    const int cnt = te - ts;              // multiply steps: 30 or 31

    const float4* ap = (const float4*)(la + (size_t)(tile0 + ts * N_) * 64) + i * 2 + h;
    const float*  bp = lb + (tile0 + ts * N_) * 8 + i;

    float Qx, Qy;
    {   // Q = M_ts
        float4 a4 = *ap;
        float  biL = (*bp) * L2E;
        float ax = (q & 1) ? a4.z : a4.x;
        float ay = (q & 1) ? a4.w : a4.y;
        Qx = ex2f(fmaf(ax, L2E, biL));
        Qy = ex2f(fmaf(ay, L2E, biL));
        ap += 16 * N_; bp += 8 * N_;
    }

    // depth-2 prefetch buffers (cnt >= 30 always)
    float4 a4x = ap[0];        float bix = bp[0];
    float4 a4y = ap[16 * N_];  float biy = bp[8 * N_];
    ap += 32 * N_; bp += 16 * N_;

    int rcnt = 0;
    auto mstep = [&](float4 a4, float bi) {
        float biL = bi * L2E;
        float m0 = ex2f(fmaf(a4.x, L2E, biL));
        float m1 = ex2f(fmaf(a4.y, L2E, biL));
        float m2 = ex2f(fmaf(a4.z, L2E, biL));
        float m3 = ex2f(fmaf(a4.w, L2E, biL));
        float o0 = __shfl_xor_sync(FULLMASK, m0, 2);
        float o1 = __shfl_xor_sync(FULLMASK, m1, 2);
        float o2 = __shfl_xor_sync(FULLMASK, m2, 2);
        float o3 = __shfl_xor_sync(FULLMASK, m3, 2);

        float nx = 0.f, ny = 0.f;
        {   // local half: l = 4h + cc
            float qx, qy;
            qx = __shfl_sync(FULLMASK, Qx, srcL);      qy = __shfl_sync(FULLMASK, Qy, srcL);
            nx = fmaf(m0, qx, nx); ny = fmaf(m0, qy, ny);
            qx = __shfl_sync(FULLMASK, Qx, srcL + 4);  qy = __shfl_sync(FULLMASK, Qy, srcL + 4);
            nx = fmaf(m1, qx, nx); ny = fmaf(m1, qy, ny);
            qx = __shfl_sync(FULLMASK, Qx, srcL + 8);  qy = __shfl_sync(FULLMASK, Qy, srcL + 8);
            nx = fmaf(m2, qx, nx); ny = fmaf(m2, qy, ny);
            qx = __shfl_sync(FULLMASK, Qx, srcL + 12); qy = __shfl_sync(FULLMASK, Qy, srcL + 12);
            nx = fmaf(m3, qx, nx); ny = fmaf(m3, qy, ny);
        }
        {   // remote half: l = 4(1-h) + cc
            float qx, qy;
            qx = __shfl_sync(FULLMASK, Qx, srcR);      qy = __shfl_sync(FULLMASK, Qy, srcR);
            nx = fmaf(o0, qx, nx); ny = fmaf(o0, qy, ny);
            qx = __shfl_sync(FULLMASK, Qx, srcR + 4);  qy = __shfl_sync(FULLMASK, Qy, srcR + 4);
            nx = fmaf(o1, qx, nx); ny = fmaf(o1, qy, ny);
            qx = __shfl_sync(FULLMASK, Qx, srcR + 8);  qy = __shfl_sync(FULLMASK, Qy, srcR + 8);
            nx = fmaf(o2, qx, nx); ny = fmaf(o2, qy, ny);
            qx = __shfl_sync(FULLMASK, Qx, srcR + 12); qy = __shfl_sync(FULLMASK, Qy, srcR + 12);
            nx = fmaf(o3, qx, nx); ny = fmaf(o3, qy, ny);
        }
        Qx = nx; Qy = ny;
        ++rcnt;
        if ((rcnt & 3) == 0 || rcnt == cnt) {  // rescale every 4 + final
            float m = fmaxf(Qx, Qy);
            m = fmaxf(m, __shfl_xor_sync(FULLMASK, m, 1));
            m = fmaxf(m, __shfl_xor_sync(FULLMASK, m, 2));
            m = fmaxf(m, __shfl_xor_sync(FULLMASK, m, 4));
            m = fmaxf(m, __shfl_xor_sync(FULLMASK, m, 8));
            m = fmaxf(m, __shfl_xor_sync(FULLMASK, m, 16));
            float inv = rcpf(m);
            Qx *= inv; Qy *= inv;
        }
    };

    for (int u = 0; u + 2 <= cnt; u += 2) {
        float4 a = a4x; float bb = bix;
        if (u + 2 < cnt) { a4x = *ap; bix = *bp; ap += 16 * N_; bp += 8 * N_; }
        mstep(a, bb);
        a = a4y; bb = biy;
        if (u + 3 < cnt) { a4y = *ap; biy = *bp; ap += 16 * N_; bp += 8 * N_; }
        mstep(a, bb);
    }
    if (cnt & 1) mstep(a4x, bix);

    *(float2*)(g_Q + (size_t)(c * S_ + s) * 64 + lane * 2) = make_float2(Qx, Qy);
}

// ---------------------------------------------------------------------------
// pass2: sequential scan over segments. warp = (dir, chain).  (R12 verbatim)
// ---------------------------------------------------------------------------
__global__ void __launch_bounds__(128) pass2_kernel(
    const float* __restrict__ lb, const float* __restrict__ lz)
{
    const int w    = blockIdx.x * 4 + (threadIdx.x >> 5);
    const int lane = threadIdx.x & 31;
    const int q    = lane & 3;
    const int i    = lane >> 2;
    const bool is_bw = (w >= C_);
    const int c = is_bw ? w - C_ : w;
    const int b = c >> 6, n = c & 63;
    const int tile0 = b * TN + n;

    if (!is_bw) {
        float x = lz[n * 8 + i] + lb[tile0 * 8 + i];
        float m0 = x;
        m0 = fmaxf(m0, __shfl_xor_sync(FULLMASK, m0, 4));
        m0 = fmaxf(m0, __shfl_xor_sync(FULLMASK, m0, 8));
        m0 = fmaxf(m0, __shfl_xor_sync(FULLMASK, m0, 16));
        float vi = ex2f((x - m0) * L2E);       // v[i], replicated over q

        for (int s = 0; s <= 30; s++) {
            float2 Qr = *(const float2*)(g_Q + (size_t)(c * S_ + s) * 64 + lane * 2);
            float vx = __shfl_sync(FULLMASK, vi, 8 * q);
            float vy = __shfl_sync(FULLMASK, vi, 8 * q + 4);
            float p = fmaf(Qr.x, vx, Qr.y * vy);
            p += __shfl_xor_sync(FULLMASK, p, 1);
            p += __shfl_xor_sync(FULLMASK, p, 2);
            float m = p;
            m = fmaxf(m, __shfl_xor_sync(FULLMASK, m, 4));
            m = fmaxf(m, __shfl_xor_sync(FULLMASK, m, 8));
            m = fmaxf(m, __shfl_xor_sync(FULLMASK, m, 16));
            vi = p * rcpf(m);
            if (q == 0) g_Vb[(size_t)(c * S_ + s + 1) * 8 + i] = vi;
        }
    } else {
        float ri = 1.0f;
        for (int s = 31; s >= 1; s--) {
            float2 Qr = *(const float2*)(g_Q + (size_t)(c * S_ + s) * 64 + lane * 2);
            float pe = Qr.x * ri;
            float po = Qr.y * ri;
            pe += __shfl_xor_sync(FULLMASK, pe, 4);
            pe += __shfl_xor_sync(FULLMASK, pe, 8);
            pe += __shfl_xor_sync(FULLMASK, pe, 16);
            po += __shfl_xor_sync(FULLMASK, po, 4);
            po += __shfl_xor_sync(FULLMASK, po, 8);
            po += __shfl_xor_sync(FULLMASK, po, 16);
            float re = __shfl_sync(FULLMASK, pe, i >> 1);
            float ro = __shfl_sync(FULLMASK, po, i >> 1);
            float rn = (i & 1) ? ro : re;
            float m = fmaxf(pe, po);
            m = fmaxf(m, __shfl_xor_sync(FULLMASK, m, 1));
            m = fmaxf(m, __shfl_xor_sync(FULLMASK, m, 2));
            ri = rn * rcpf(m);
            if (q == 0) g_Rb[(size_t)(c * S_ + s) * 8 + i] = ri;
        }
    }
}

// ---------------------------------------------------------------------------
// fwbwgamma: forward recursion (alphas cached in SMEM, 1KB/warp), then
// backward recursion + all output emission in the same warp. (R12 verbatim)
// ---------------------------------------------------------------------------
__global__ void __launch_bounds__(128) fwbwgamma_kernel(
    const float* __restrict__ la, const float* __restrict__ lb,
    const float* __restrict__ lz,
    float* __restrict__ fw, float* __restrict__ bwo,
    float* __restrict__ g1, float* __restrict__ g2)
{
    __shared__ float sfw[4 * 264];          // 264-stride staggers banks per warp
    const int wl   = threadIdx.x >> 5;
    const int w    = blockIdx.x * 4 + wl;
    const int lane = threadIdx.x & 31;
    const int ii   = lane & 3;
    const int rr   = lane >> 2;
    const int c = w >> 5, s = w & 31;
    const int b = c >> 6, n = c & 63;
    const int tile0 = b * TN + n;
    const int sel0 = ii * 8, sel1 = ii * 8 + 4;
    const int sL = s * L_;
    const int te = sL + L_ - 1;
    float* fc = sfw + wl * 264;             // fwu cache: [tloc][rr]

    // ===================== forward sweep =====================
    {
        float prev;
        int t0;
        if (s == 0) {
            prev = (lz[n * 8 + rr] + lb[tile0 * 8 + rr]) * L2E;
            if (ii == 0) fc[rr] = prev;     // tloc 0
            t0 = 1;
        } else {
            prev = lg2f(g_Vb[(c * S_ + s) * 8 + rr]);
            t0 = sL;
        }
        const int cnt = te - t0 + 1;        // 31 or 32

        const float2* ap = (const float2*)la + (tile0 + t0 * N_) * 32 + lane;
        const float*  bp = lb + (tile0 + t0 * N_) * 8 + rr;
        float*        op = fc + (t0 - sL) * 8 + rr;

        float2 avx = ap[0];       float bvx = bp[0];
        float2 avy = ap[32 * N_]; float bvy = bp[8 * N_];
        ap += 64 * N_; bp += 16 * N_;

        auto fstep = [&](float2 av, float bv) {
            float p0 = __shfl_sync(FULLMASK, prev, sel0);
            float p1 = __shfl_sync(FULLMASK, prev, sel1);
            float u0 = __shfl_sync(FULLMASK, prev, 0);
            float e = ex2f(fmaf(av.x, L2E, p0 - u0))
                    + ex2f(fmaf(av.y, L2E, p1 - u0));
            e += __shfl_xor_sync(FULLMASK, e, 1);
            e += __shfl_xor_sync(FULLMASK, e, 2);
            float uu = fmaf(bv, L2E, lg2f(e));
            prev = uu;
            if (ii == 0) *op = uu;
            op += 8;
        };

        for (int u = 0; u + 2 <= cnt; u += 2) {
            float2 a = avx; float bb = bvx;
            if (u + 2 < cnt) { avx = *ap; bvx = *bp; ap += 32 * N_; bp += 8 * N_; }
            fstep(a, bb);
            a = avy; bb = bvy;
            if (u + 3 < cnt) { avy = *ap; bvy = *bp; ap += 32 * N_; bp += 8 * N_; }
            fstep(a, bb);
        }
        if (cnt & 1) fstep(avx, bvx);
    }
    __syncwarp();

    // ===================== backward + emission sweep =====================
    const int lnZ = lane | 3;               // same rr, ii=3 lane
    const bool top = (s == 31);

    float prev  = top ? 0.0f : lg2f(g_Rb[(c * S_ + s + 1) * 8 + rr]);
    float fprev = fc[31 * 8 + rr];          // fwu[te]

    const float*  cp  = la + (size_t)(tile0 + te * N_) * 64 + ii * 16 + rr;
    const float2* bp2 = (const float2*)lb + (tile0 + te * N_) * 4 + ii;
    const float*  fp  = fc + 30 * 8 + rr;   // fwu[te-1]
    int ob  = (tile0 + te * N_) * 8 + rr;   // fw/bw/g1 (per-ii predication)
    int g2b = (tile0 + te * N_) * 64;       // gamma2 tile base

    // depth-2 prefetch (31 iterations always)
    float c0x = cp[0], c1x = cp[8];
    float2 bvx = bp2[0];
    float fcx = fp[0];
    float c0y = cp[-64 * N_], c1y = cp[-64 * N_ + 8];
    float2 bvy = bp2[-4 * N_];
    float fcy = fp[-8];
    cp -= 128 * N_; bp2 -= 8 * N_; fp -= 16;

    auto step = [&](float c0, float c1, float2 bv, float fcur, bool first) {
        // recursion core (beta_{t+1} -> beta_t)
        float p0 = __shfl_sync(FULLMASK, prev, sel0);
        float p1 = __shfl_sync(FULLMASK, prev, sel1);
        float u0 = __shfl_sync(FULLMASK, prev, 0);
        float a0 = fmaf(c0 + bv.x, L2E, p0 - u0);
        float a1 = fmaf(c1 + bv.y, L2E, p1 - u0);
        float e  = ex2f(a0) + ex2f(a1);
        e += __shfl_xor_sync(FULLMASK, e, 1);
        e += __shfl_xor_sync(FULLMASK, e, 2);   // e(rr) = sum over i

        // unified emission reduction for time t+1 (per-ii operand)
        float val = (ii == 0) ? prev
                  : (ii == 1) ? fprev
                  : (ii == 2) ? (fprev + prev) : fcur;
        float ee = ex2f(val);
        if (ii == 3) ee *= e;                   // gamma2 Z terms
        ee += __shfl_xor_sync(FULLMASK, ee, 4);
        ee += __shfl_xor_sync(FULLMASK, ee, 8);
        ee += __shfl_xor_sync(FULLMASK, ee, 16);
        float lgE = lg2f(ee);                   // per-ii normalizer
        float lgZ = __shfl_sync(FULLMASK, lgE, lnZ);

        float outv = (val - lgE) * LN2;
        if (ii == 0) bwo[ob] = (top && first) ? 0.0f : outv;
        else if (ii == 1) fw[ob] = outv;
        else if (ii == 2) g1[ob] = outv;

        float tt2 = (fcur - lgZ) * LN2;
        g2[g2b + 16 * ii + rr]     = fmaf(a0, LN2, tt2);
        g2[g2b + 16 * ii + 8 + rr] = fmaf(a1, LN2, tt2);

        prev  = lg2f(e);
        fprev = fcur;
        ob -= 8 * N_; g2b -= 64 * N_;
    };

    for (int u = 0; u + 2 <= 31; u += 2) {
        {
            float c0 = c0x, c1 = c1x; float2 bv = bvx; float fcv = fcx;
            if (u + 2 < 31) {
                c0x = cp[0]; c1x = cp[8]; bvx = bp2[0]; fcx = fp[0];
                cp -= 64 * N_; bp2 -= 4 * N_; fp -= 8;
            }
            step(c0, c1, bv, fcv, u == 0);
        }
        {
            float c0 = c0y, c1 = c1y; float2 bv = bvy; float fcv = fcy;
            if (u + 3 < 31) {
                c0y = cp[0]; c1y = cp[8]; bvy = bp2[0]; fcy = fp[0];
                cp -= 64 * N_; bp2 -= 4 * N_; fp -= 8;
            }
            step(c0, c1, bv, fcv, false);
        }
    }
    step(c0x, c1x, bvx, fcx, false);           // iteration 30 (odd leftover)

    // ---- tail emission for time t = sL (prev = beta_{sL}, fprev = fwu[sL]) ----
    {
        float a0t = 0.f, a1t = 0.f, et = 1.0f, fct = 0.f;
        if (s != 0) {
            const float* cpe = la + (size_t)(tile0 + sL * N_) * 64 + ii * 16 + rr;
            float  c0 = cpe[0];
            float  c1 = cpe[8];
            float2 bv = *((const float2*)lb + (tile0 + sL * N_) * 4 + ii);
            fct = lg2f(g_Vb[(c * S_ + s) * 8 + rr]);     // fwu[sL-1] (shifted)
            float p0 = __shfl_sync(FULLMASK, prev, sel0);
            float p1 = __shfl_sync(FULLMASK, prev, sel1);
            float u0 = __shfl_sync(FULLMASK, prev, 0);
            a0t = fmaf(c0 + bv.x, L2E, p0 - u0);
            a1t = fmaf(c1 + bv.y, L2E, p1 - u0);
            et  = ex2f(a0t) + ex2f(a1t);
            et += __shfl_xor_sync(FULLMASK, et, 1);
            et += __shfl_xor_sync(FULLMASK, et, 2);
        }
        float val = (ii == 0) ? prev
                  : (ii == 1) ? fprev
                  : (ii == 2) ? (fprev + prev) : fct;
        float ee = ex2f(val);
        if (ii == 3) ee *= et;
        ee += __shfl_xor_sync(FULLMASK, ee, 4);
        ee += __shfl_xor_sync(FULLMASK, ee, 8);
        ee += __shfl_xor_sync(FULLMASK, ee, 16);
        float lgE = lg2f(ee);
        float lgZ = __shfl_sync(FULLMASK, lgE, lnZ);

        float outv = (val - lgE) * LN2;
        if (ii == 0) bwo[ob] = outv;
        else if (ii == 1) fw[ob] = outv;
        else if (ii == 2) g1[ob] = outv;

        if (s == 0) {                            // gamma2[0] = zeros
            g2[g2b + 16 * ii + rr]     = 0.0f;
            g2[g2b + 16 * ii + 8 + rr] = 0.0f;
        } else {
            float tt2 = (fct - lgZ) * LN2;
            g2[g2b + 16 * ii + rr]     = fmaf(a0t, LN2, tt2);
            g2[g2b + 16 * ii + 8 + rr] = fmaf(a1t, LN2, tt2);
        }
    }
}

extern "C" void kernel_launch(void* const* d_in, const int* in_sizes, int n_in,
                              void* d_out, int out_size) {
    const float* la = (const float*)d_in[0];   // log_a  (B,T,N,K,K)
    const float* lb = (const float*)d_in[1];   // log_b  (B,T,N,K)
    const float* lz = (const float*)d_in[2];   // logprob_z1 (N,K)

    float* out = (float*)d_out;
    float* fw = out;
    float* bw = fw + BTNK;
    float* g1 = bw + BTNK;
    float* g2 = g1 + BTNK;

    pass1_kernel<<<(C_ * S_) / 4, 128>>>(la, lb);              // 16384 warps
    pass2_kernel<<<(2 * C_) / 4, 128>>>(lb, lz);               // 1024 warps
    fwbwgamma_kernel<<<(C_ * S_) / 4, 128>>>(la, lb, lz, fw, bw, g1, g2);
}